// round 8
// baseline (speedup 1.0000x reference)
#include <cuda_runtime.h>
#include <cuda_fp16.h>
#include <cstdint>

#define DIN   4096
#define DOUT  4096
#define MTOT  8192
#define BM    128
#define BN    128
#define BK    32
#define NKT   (DIN / BK)      // 128
#define STAGES 4
#define ASTAGE 10240          // 128 rows * 5 chunks * 16B (padded)
#define STAGEB 20480          // A + B per stage

// Packed fp16 operand tiles. Tile (mb,kt) / (nb,kt) = 4096 halves contiguous,
// chunk c (16B, 8 halves) = row (c>>2), kchunk (c&3). A: [M][K]; B: [N][K] (W transposed).
__device__ __half g_A[(size_t)MTOT * DIN];
__device__ __half g_B[(size_t)DOUT * DIN];

__device__ __forceinline__ uint32_t smem_u32(const void* p) {
    uint32_t a;
    asm("{ .reg .u64 t; cvta.to.shared.u64 t, %1; cvt.u32.u64 %0, t; }" : "=r"(a) : "l"(p));
    return a;
}
__device__ __forceinline__ void cp16(uint32_t dst, const void* src) {
    asm volatile("cp.async.cg.shared.global [%0], [%1], 16;\n" :: "r"(dst), "l"(src));
}

// ---------- pack x -> fp16 tiles ----------
__global__ void __launch_bounds__(256) pack_x(const float* __restrict__ x) {
    int mb = blockIdx.x, kt = blockIdx.y;
    __half* tile = g_A + ((size_t)(mb * NKT + kt) << 12);
    #pragma unroll
    for (int it = 0; it < 2; it++) {
        int cid = it * 256 + threadIdx.x;            // 512 chunks of 8 halves
        int row = cid >> 2, kc = cid & 3;
        const float4* src = (const float4*)(x + (size_t)(mb * 128 + row) * DIN + kt * BK + kc * 8);
        float4 f0 = src[0], f1 = src[1];
        __half2 h0 = __floats2half2_rn(f0.x, f0.y);
        __half2 h1 = __floats2half2_rn(f0.z, f0.w);
        __half2 h2 = __floats2half2_rn(f1.x, f1.y);
        __half2 h3 = __floats2half2_rn(f1.z, f1.w);
        uint4 v;
        v.x = *(uint32_t*)&h0; v.y = *(uint32_t*)&h1;
        v.z = *(uint32_t*)&h2; v.w = *(uint32_t*)&h3;
        *(uint4*)(tile + cid * 8) = v;
    }
}

// ---------- fuse W = base + c*sign, transpose to [N][K] fp16 tiles ----------
__global__ void __launch_bounds__(256) pack_w(const float* __restrict__ base,
                                              const int* __restrict__ mask,
                                              const float* __restrict__ coeff) {
    __shared__ uint32_t sw32[128 * 17];              // [n][kpair], pad 17
    int nb = blockIdx.x, kt = blockIdx.y;
    int t = threadIdx.x;
    float c = __ldg(coeff);
    int n = t & 127, hsel = t >> 7;
    #pragma unroll
    for (int i = 0; i < 8; i++) {
        int kp = hsel * 8 + i;
        size_t off0 = (size_t)(kt * BK + kp * 2) * DOUT + nb * 128 + n;
        size_t off1 = off0 + DOUT;
        float w0 = base[off0] + (mask[off0] ? c : -c);
        float w1 = base[off1] + (mask[off1] ? c : -c);
        __half2 h = __floats2half2_rn(w0, w1);
        sw32[n * 17 + kp] = *(uint32_t*)&h;
    }
    __syncthreads();
    __half* tile = g_B + ((size_t)(nb * NKT + kt) << 12);
    #pragma unroll
    for (int it = 0; it < 2; it++) {
        int cid = it * 256 + t;
        int nn = cid >> 2, kc = cid & 3;
        uint4 v;
        v.x = sw32[nn * 17 + kc * 4 + 0];
        v.y = sw32[nn * 17 + kc * 4 + 1];
        v.z = sw32[nn * 17 + kc * 4 + 2];
        v.w = sw32[nn * 17 + kc * 4 + 3];
        *(uint4*)(tile + cid * 8) = v;
    }
}

// ---------- fp16 GEMM: 4 warps, warp tile 64x64, 1 barrier per 2 k-tiles ----------
__global__ void __launch_bounds__(128, 2) gemm_fp16(float* __restrict__ out) {
    extern __shared__ char smem[];
    const uint32_t sbase = smem_u32(smem);

    const int tid  = threadIdx.x;
    const int lane = tid & 31;
    const int warp = tid >> 5;                // 0..3
    const int wm = (warp & 1) * 64;           // warp tile 64(m) x 64(n)
    const int wn = (warp >> 1) * 64;

    // L2 block swizzle: 8 m-blocks share one n-block column
    int pid = blockIdx.x;
    int local = pid & 255, g = pid >> 8;
    int bm = (g << 3) + (local & 7);
    int bn = local >> 3;

    const __half* tA0 = g_A + ((size_t)bm * NKT << 12);
    const __half* tB0 = g_B + ((size_t)bn * NKT << 12);

    // ldmatrix per-lane base offsets (padded stride-5-chunk layout)
    const int j = lane >> 3, sub = lane & 7;
    uint32_t aoff[4], boff[4];
    #pragma unroll
    for (int mt = 0; mt < 4; mt++) {
        int m = wm + mt * 16 + (j & 1) * 8 + sub;
        aoff[mt] = (uint32_t)((m * 5 + (j >> 1)) << 4);
    }
    #pragma unroll
    for (int np = 0; np < 4; np++) {
        int n = wn + np * 16 + (j >> 1) * 8 + sub;
        boff[np] = (uint32_t)((n * 5 + (j & 1)) << 4) + ASTAGE;
    }

    float acc[4][8][4];
    #pragma unroll
    for (int a = 0; a < 4; a++)
        #pragma unroll
        for (int b = 0; b < 8; b++)
            #pragma unroll
            for (int d = 0; d < 4; d++) acc[a][b][d] = 0.f;

    auto issue = [&](int kt, int stage) {
        const __half* tA = tA0 + ((size_t)kt << 12);
        const __half* tB = tB0 + ((size_t)kt << 12);
        #pragma unroll
        for (int it = 0; it < 4; it++) {
            int cid = it * 128 + tid;             // 512 chunks each
            uint32_t d = sbase + stage * STAGEB + ((((cid >> 2) * 5) + (cid & 3)) << 4);
            cp16(d, tA + cid * 8);
            cp16(d + ASTAGE, tB + cid * 8);
        }
        asm volatile("cp.async.commit_group;\n");
    };

    auto compute = [&](int stage) {
        const uint32_t st = sbase + stage * STAGEB;
        #pragma unroll
        for (int ks = 0; ks < 2; ks++) {
            uint32_t a[4][4], b[4][4];
            #pragma unroll
            for (int mt = 0; mt < 4; mt++)
                asm volatile("ldmatrix.sync.aligned.m8n8.x4.shared.b16 {%0,%1,%2,%3}, [%4];"
                             : "=r"(a[mt][0]), "=r"(a[mt][1]), "=r"(a[mt][2]), "=r"(a[mt][3])
                             : "r"(st + aoff[mt] + ks * 32));
            #pragma unroll
            for (int np = 0; np < 4; np++)
                asm volatile("ldmatrix.sync.aligned.m8n8.x4.shared.b16 {%0,%1,%2,%3}, [%4];"
                             : "=r"(b[np][0]), "=r"(b[np][1]), "=r"(b[np][2]), "=r"(b[np][3])
                             : "r"(st + boff[np] + ks * 32));
            #pragma unroll
            for (int mt = 0; mt < 4; mt++)
                #pragma unroll
                for (int np = 0; np < 4; np++)
                    #pragma unroll
                    for (int h = 0; h < 2; h++) {
                        float* d = acc[mt][np * 2 + h];
                        asm volatile(
                            "mma.sync.aligned.m16n8k16.row.col.f32.f16.f16.f32 "
                            "{%0,%1,%2,%3}, {%4,%5,%6,%7}, {%8,%9}, {%0,%1,%2,%3};\n"
                            : "+f"(d[0]), "+f"(d[1]), "+f"(d[2]), "+f"(d[3])
                            : "r"(a[mt][0]), "r"(a[mt][1]), "r"(a[mt][2]), "r"(a[mt][3]),
                              "r"(b[np][2 * h]), "r"(b[np][2 * h + 1]));
                    }
        }
    };

    // prologue: first pair in flight
    issue(0, 0); issue(1, 1);

    // mainloop: pairs of k-tiles; one wait + one barrier per pair.
    // Top of iteration kt (even): pending groups = {kt, kt+1}.
    // Stages (kt+2)&3, (kt+3)&3 were last READ in iteration kt-2, and every
    // warp passed this barrier since then -> safe to overwrite.
    #pragma unroll 1
    for (int kt = 0; kt < NKT; kt += 2) {
        asm volatile("cp.async.wait_group 0;\n");
        __syncthreads();
        if (kt + 2 < NKT) issue(kt + 2, (kt + 2) & 3);
        if (kt + 3 < NKT) issue(kt + 3, (kt + 3) & 3);
        compute(kt & 3);
        compute((kt + 1) & 3);
    }

    // epilogue
    const int r = lane >> 2, cc = lane & 3;
    #pragma unroll
    for (int mt = 0; mt < 4; mt++) {
        #pragma unroll
        for (int n8 = 0; n8 < 8; n8++) {
            size_t row = (size_t)bm * BM + wm + mt * 16 + r;
            size_t col = (size_t)bn * BN + wn + n8 * 8 + cc * 2;
            float* d = acc[mt][n8];
            *(float2*)(out + row * DOUT + col)       = make_float2(d[0], d[1]);
            *(float2*)(out + (row + 8) * DOUT + col) = make_float2(d[2], d[3]);
        }
    }
}

extern "C" void kernel_launch(void* const* d_in, const int* in_sizes, int n_in,
                              void* d_out, int out_size) {
    const float* x     = (const float*)d_in[0];
    const float* base  = (const float*)d_in[1];
    const int*   mask  = (const int*)d_in[2];
    const float* coeff = (const float*)d_in[3];
    float* out = (float*)d_out;

    pack_x<<<dim3(MTOT / 128, NKT), 256>>>(x);
    pack_w<<<dim3(DOUT / 128, NKT), 256>>>(base, mask, coeff);

    const int smem = STAGES * STAGEB;   // 81920
    cudaFuncSetAttribute(gemm_fp16, cudaFuncAttributeMaxDynamicSharedMemorySize, smem);
    gemm_fp16<<<(MTOT / BM) * (DOUT / BN), 128, smem>>>(out);
}

// round 9
// speedup vs baseline: 1.2625x; 1.2625x over previous
#include <cuda_runtime.h>
#include <cuda_fp16.h>
#include <cstdint>

#define DIN   4096
#define DOUT  4096
#define MTOT  8192
#define BM    128
#define BN    128
#define BK    32
#define NKT   (DIN / BK)      // 128
#define STAGES 4
#define ASTAGE 10240          // 128 rows * 5 chunks * 16B (padded)
#define STAGEB 20480          // A + B per stage

// Packed fp16 operand tiles. Tile (mb,kt) / (nb,kt) = 4096 halves contiguous,
// chunk c (16B, 8 halves) = row (c>>2), kchunk (c&3). A: [M][K]; B: [N][K] (W transposed).
__device__ __half g_A[(size_t)MTOT * DIN];
__device__ __half g_B[(size_t)DOUT * DIN];

__device__ __forceinline__ uint32_t smem_u32(const void* p) {
    uint32_t a;
    asm("{ .reg .u64 t; cvta.to.shared.u64 t, %1; cvt.u32.u64 %0, t; }" : "=r"(a) : "l"(p));
    return a;
}
__device__ __forceinline__ void cp16(uint32_t dst, const void* src) {
    asm volatile("cp.async.cg.shared.global [%0], [%1], 16;\n" :: "r"(dst), "l"(src));
}

// ---------- pack x -> fp16 tiles ----------
__global__ void __launch_bounds__(256) pack_x(const float* __restrict__ x) {
    int mb = blockIdx.x, kt = blockIdx.y;
    __half* tile = g_A + ((size_t)(mb * NKT + kt) << 12);
    #pragma unroll
    for (int it = 0; it < 2; it++) {
        int cid = it * 256 + threadIdx.x;            // 512 chunks of 8 halves
        int row = cid >> 2, kc = cid & 3;
        const float4* src = (const float4*)(x + (size_t)(mb * 128 + row) * DIN + kt * BK + kc * 8);
        float4 f0 = src[0], f1 = src[1];
        __half2 h0 = __floats2half2_rn(f0.x, f0.y);
        __half2 h1 = __floats2half2_rn(f0.z, f0.w);
        __half2 h2 = __floats2half2_rn(f1.x, f1.y);
        __half2 h3 = __floats2half2_rn(f1.z, f1.w);
        uint4 v;
        v.x = *(uint32_t*)&h0; v.y = *(uint32_t*)&h1;
        v.z = *(uint32_t*)&h2; v.w = *(uint32_t*)&h3;
        *(uint4*)(tile + cid * 8) = v;
    }
}

// ---------- fuse W = base + c*sign, transpose to [N][K] fp16 tiles ----------
__global__ void __launch_bounds__(256) pack_w(const float* __restrict__ base,
                                              const int* __restrict__ mask,
                                              const float* __restrict__ coeff) {
    __shared__ uint32_t sw32[128 * 17];              // [n][kpair], pad 17
    int nb = blockIdx.x, kt = blockIdx.y;
    int t = threadIdx.x;
    float c = __ldg(coeff);
    int n = t & 127, hsel = t >> 7;
    #pragma unroll
    for (int i = 0; i < 8; i++) {
        int kp = hsel * 8 + i;
        size_t off0 = (size_t)(kt * BK + kp * 2) * DOUT + nb * 128 + n;
        size_t off1 = off0 + DOUT;
        float w0 = base[off0] + (mask[off0] ? c : -c);
        float w1 = base[off1] + (mask[off1] ? c : -c);
        __half2 h = __floats2half2_rn(w0, w1);
        sw32[n * 17 + kp] = *(uint32_t*)&h;
    }
    __syncthreads();
    __half* tile = g_B + ((size_t)(nb * NKT + kt) << 12);
    #pragma unroll
    for (int it = 0; it < 2; it++) {
        int cid = it * 256 + t;
        int nn = cid >> 2, kc = cid & 3;
        uint4 v;
        v.x = sw32[nn * 17 + kc * 4 + 0];
        v.y = sw32[nn * 17 + kc * 4 + 1];
        v.z = sw32[nn * 17 + kc * 4 + 2];
        v.w = sw32[nn * 17 + kc * 4 + 3];
        *(uint4*)(tile + cid * 8) = v;
    }
}

// ---------- fp16 GEMM: 4 warps, 64x64 warp tiles, 1 barrier per k-tile ----------
__global__ void __launch_bounds__(128, 2) gemm_fp16(float* __restrict__ out) {
    extern __shared__ char smem[];
    const uint32_t sbase = smem_u32(smem);

    const int tid  = threadIdx.x;
    const int lane = tid & 31;
    const int warp = tid >> 5;                // 0..3
    const int wm = (warp & 1) * 64;           // warp tile 64(m) x 64(n)
    const int wn = (warp >> 1) * 64;

    // L2 block swizzle: 8 m-blocks share one n-block column
    int pid = blockIdx.x;
    int local = pid & 255, g = pid >> 8;
    int bm = (g << 3) + (local & 7);
    int bn = local >> 3;

    const __half* tA0 = g_A + ((size_t)bm * NKT << 12);
    const __half* tB0 = g_B + ((size_t)bn * NKT << 12);

    // ldmatrix per-lane base offsets (padded stride-5-chunk layout)
    const int j = lane >> 3, sub = lane & 7;
    uint32_t aoff[4], boff[4];
    #pragma unroll
    for (int mt = 0; mt < 4; mt++) {
        int m = wm + mt * 16 + (j & 1) * 8 + sub;
        aoff[mt] = (uint32_t)((m * 5 + (j >> 1)) << 4);
    }
    #pragma unroll
    for (int np = 0; np < 4; np++) {
        int n = wn + np * 16 + (j >> 1) * 8 + sub;
        boff[np] = (uint32_t)((n * 5 + (j & 1)) << 4) + ASTAGE;
    }

    float acc[4][8][4];
    #pragma unroll
    for (int a = 0; a < 4; a++)
        #pragma unroll
        for (int b = 0; b < 8; b++)
            #pragma unroll
            for (int d = 0; d < 4; d++) acc[a][b][d] = 0.f;

    auto issue = [&](int kt, int stage) {
        const __half* tA = tA0 + ((size_t)kt << 12);
        const __half* tB = tB0 + ((size_t)kt << 12);
        #pragma unroll
        for (int it = 0; it < 4; it++) {
            int cid = it * 128 + tid;             // 512 chunks each
            uint32_t d = sbase + stage * STAGEB + ((((cid >> 2) * 5) + (cid & 3)) << 4);
            cp16(d, tA + cid * 8);
            cp16(d + ASTAGE, tB + cid * 8);
        }
        asm volatile("cp.async.commit_group;\n");
    };

    // prologue: stages 0,1,2 in flight
    issue(0, 0); issue(1, 1); issue(2, 2);

    // mainloop (cutlass multistage): one wait + one barrier per k-tile,
    // 3-deep lookahead. At top of iter kt: pending = {kt, kt+1, kt+2}.
    // wait_group 2 -> group kt complete. issue targets stage (kt+3)&3 ==
    // (kt-1)&3, consumed by all warps before this iteration's barrier.
    #pragma unroll 1
    for (int kt = 0; kt < NKT; kt++) {
        if (kt + 2 < NKT) asm volatile("cp.async.wait_group 2;\n");
        else              asm volatile("cp.async.wait_group 0;\n");
        __syncthreads();
        if (kt + 3 < NKT) issue(kt + 3, (kt + 3) & 3);

        const uint32_t st = sbase + (kt & 3) * STAGEB;
        // load ALL fragments for both ks halves up front (64 frag regs)
        uint32_t a[2][4][4], b[2][4][4];
        #pragma unroll
        for (int ks = 0; ks < 2; ks++) {
            #pragma unroll
            for (int mt = 0; mt < 4; mt++)
                asm volatile("ldmatrix.sync.aligned.m8n8.x4.shared.b16 {%0,%1,%2,%3}, [%4];"
                             : "=r"(a[ks][mt][0]), "=r"(a[ks][mt][1]),
                               "=r"(a[ks][mt][2]), "=r"(a[ks][mt][3])
                             : "r"(st + aoff[mt] + ks * 32));
            #pragma unroll
            for (int np = 0; np < 4; np++)
                asm volatile("ldmatrix.sync.aligned.m8n8.x4.shared.b16 {%0,%1,%2,%3}, [%4];"
                             : "=r"(b[ks][np][0]), "=r"(b[ks][np][1]),
                               "=r"(b[ks][np][2]), "=r"(b[ks][np][3])
                             : "r"(st + boff[np] + ks * 32));
        }
        #pragma unroll
        for (int ks = 0; ks < 2; ks++)
            #pragma unroll
            for (int mt = 0; mt < 4; mt++)
                #pragma unroll
                for (int np = 0; np < 4; np++)
                    #pragma unroll
                    for (int h = 0; h < 2; h++) {
                        float* d = acc[mt][np * 2 + h];
                        asm volatile(
                            "mma.sync.aligned.m16n8k16.row.col.f32.f16.f16.f32 "
                            "{%0,%1,%2,%3}, {%4,%5,%6,%7}, {%8,%9}, {%0,%1,%2,%3};\n"
                            : "+f"(d[0]), "+f"(d[1]), "+f"(d[2]), "+f"(d[3])
                            : "r"(a[ks][mt][0]), "r"(a[ks][mt][1]),
                              "r"(a[ks][mt][2]), "r"(a[ks][mt][3]),
                              "r"(b[ks][np][2 * h]), "r"(b[ks][np][2 * h + 1]));
                    }
    }

    // epilogue
    const int r = lane >> 2, cc = lane & 3;
    #pragma unroll
    for (int mt = 0; mt < 4; mt++) {
        #pragma unroll
        for (int n8 = 0; n8 < 8; n8++) {
            size_t row = (size_t)bm * BM + wm + mt * 16 + r;
            size_t col = (size_t)bn * BN + wn + n8 * 8 + cc * 2;
            float* d = acc[mt][n8];
            *(float2*)(out + row * DOUT + col)       = make_float2(d[0], d[1]);
            *(float2*)(out + (row + 8) * DOUT + col) = make_float2(d[2], d[3]);
        }
    }
}

extern "C" void kernel_launch(void* const* d_in, const int* in_sizes, int n_in,
                              void* d_out, int out_size) {
    const float* x     = (const float*)d_in[0];
    const float* base  = (const float*)d_in[1];
    const int*   mask  = (const int*)d_in[2];
    const float* coeff = (const float*)d_in[3];
    float* out = (float*)d_out;

    pack_x<<<dim3(MTOT / 128, NKT), 256>>>(x);
    pack_w<<<dim3(DOUT / 128, NKT), 256>>>(base, mask, coeff);

    const int smem = STAGES * STAGEB;   // 81920
    cudaFuncSetAttribute(gemm_fp16, cudaFuncAttributeMaxDynamicSharedMemorySize, smem);
    gemm_fp16<<<(MTOT / BM) * (DOUT / BN), 128, smem>>>(out);
}

// round 10
// speedup vs baseline: 1.3764x; 1.0902x over previous
#include <cuda_runtime.h>
#include <cuda_fp16.h>
#include <cstdint>

#define DIN   4096
#define DOUT  4096
#define MTOT  8192
#define BM    128
#define BN    128
#define BK    32
#define NKT   (DIN / BK)      // 128
#define STAGES 4
#define ASTAGE 10240          // 128 rows * 5 chunks * 16B (padded)
#define STAGEB 20480          // A + B per stage

// Packed fp16 operand tiles. Tile (mb,kt) / (nb,kt) = 4096 halves contiguous,
// chunk c (16B, 8 halves) = row (c>>2), kchunk (c&3). A: [M][K]; B: [N][K] (W transposed).
__device__ __half g_A[(size_t)MTOT * DIN];
__device__ __half g_B[(size_t)DOUT * DIN];

__device__ __forceinline__ uint32_t smem_u32(const void* p) {
    uint32_t a;
    asm("{ .reg .u64 t; cvta.to.shared.u64 t, %1; cvt.u32.u64 %0, t; }" : "=r"(a) : "l"(p));
    return a;
}
__device__ __forceinline__ void cp16(uint32_t dst, const void* src) {
    asm volatile("cp.async.cg.shared.global [%0], [%1], 16;\n" :: "r"(dst), "l"(src));
}

// ---------- pack x -> fp16 tiles ----------
__global__ void __launch_bounds__(256) pack_x(const float* __restrict__ x) {
    int mb = blockIdx.x, kt = blockIdx.y;
    __half* tile = g_A + ((size_t)(mb * NKT + kt) << 12);
    #pragma unroll
    for (int it = 0; it < 2; it++) {
        int cid = it * 256 + threadIdx.x;            // 512 chunks of 8 halves
        int row = cid >> 2, kc = cid & 3;
        const float4* src = (const float4*)(x + (size_t)(mb * 128 + row) * DIN + kt * BK + kc * 8);
        float4 f0 = src[0], f1 = src[1];
        __half2 h0 = __floats2half2_rn(f0.x, f0.y);
        __half2 h1 = __floats2half2_rn(f0.z, f0.w);
        __half2 h2 = __floats2half2_rn(f1.x, f1.y);
        __half2 h3 = __floats2half2_rn(f1.z, f1.w);
        uint4 v;
        v.x = *(uint32_t*)&h0; v.y = *(uint32_t*)&h1;
        v.z = *(uint32_t*)&h2; v.w = *(uint32_t*)&h3;
        *(uint4*)(tile + cid * 8) = v;
    }
}

// ---------- fuse W = base + c*sign, transpose to [N][K] fp16 tiles ----------
__global__ void __launch_bounds__(256) pack_w(const float* __restrict__ base,
                                              const int* __restrict__ mask,
                                              const float* __restrict__ coeff) {
    __shared__ uint32_t sw32[128 * 17];              // [n][kpair], pad 17
    int nb = blockIdx.x, kt = blockIdx.y;
    int t = threadIdx.x;
    float c = __ldg(coeff);
    int n = t & 127, hsel = t >> 7;
    #pragma unroll
    for (int i = 0; i < 8; i++) {
        int kp = hsel * 8 + i;
        size_t off0 = (size_t)(kt * BK + kp * 2) * DOUT + nb * 128 + n;
        size_t off1 = off0 + DOUT;
        float w0 = base[off0] + (mask[off0] ? c : -c);
        float w1 = base[off1] + (mask[off1] ? c : -c);
        __half2 h = __floats2half2_rn(w0, w1);
        sw32[n * 17 + kp] = *(uint32_t*)&h;
    }
    __syncthreads();
    __half* tile = g_B + ((size_t)(nb * NKT + kt) << 12);
    #pragma unroll
    for (int it = 0; it < 2; it++) {
        int cid = it * 256 + t;
        int nn = cid >> 2, kc = cid & 3;
        uint4 v;
        v.x = sw32[nn * 17 + kc * 4 + 0];
        v.y = sw32[nn * 17 + kc * 4 + 1];
        v.z = sw32[nn * 17 + kc * 4 + 2];
        v.w = sw32[nn * 17 + kc * 4 + 3];
        *(uint4*)(tile + cid * 8) = v;
    }
}

// ---------- fp16 GEMM: 4 warps, 64x64 warp tiles, software-pipelined LDSM ----------
__global__ void __launch_bounds__(128, 2) gemm_fp16(float* __restrict__ out) {
    extern __shared__ char smem[];
    const uint32_t sbase = smem_u32(smem);

    const int tid  = threadIdx.x;
    const int lane = tid & 31;
    const int warp = tid >> 5;                // 0..3
    const int wm = (warp & 1) * 64;           // warp tile 64(m) x 64(n)
    const int wn = (warp >> 1) * 64;

    // L2 block swizzle: 8 m-blocks share one n-block column
    int pid = blockIdx.x;
    int local = pid & 255, g = pid >> 8;
    int bm = (g << 3) + (local & 7);
    int bn = local >> 3;

    const __half* tA0 = g_A + ((size_t)bm * NKT << 12);
    const __half* tB0 = g_B + ((size_t)bn * NKT << 12);

    // ldmatrix per-lane base offsets (padded stride-5-chunk layout)
    const int j = lane >> 3, sub = lane & 7;
    uint32_t aoff[4], boff[4];
    #pragma unroll
    for (int mt = 0; mt < 4; mt++) {
        int m = wm + mt * 16 + (j & 1) * 8 + sub;
        aoff[mt] = (uint32_t)((m * 5 + (j >> 1)) << 4);
    }
    #pragma unroll
    for (int np = 0; np < 4; np++) {
        int n = wn + np * 16 + (j >> 1) * 8 + sub;
        boff[np] = (uint32_t)((n * 5 + (j & 1)) << 4) + ASTAGE;
    }

    float acc[4][8][4];
    #pragma unroll
    for (int a = 0; a < 4; a++)
        #pragma unroll
        for (int b = 0; b < 8; b++)
            #pragma unroll
            for (int d = 0; d < 4; d++) acc[a][b][d] = 0.f;

    auto issue = [&](int kt, int stage) {
        const __half* tA = tA0 + ((size_t)kt << 12);
        const __half* tB = tB0 + ((size_t)kt << 12);
        #pragma unroll
        for (int it = 0; it < 4; it++) {
            int cid = it * 128 + tid;             // 512 chunks each
            uint32_t d = sbase + stage * STAGEB + ((((cid >> 2) * 5) + (cid & 3)) << 4);
            cp16(d, tA + cid * 8);
            cp16(d + ASTAGE, tB + cid * 8);
        }
        asm volatile("cp.async.commit_group;\n");
    };

    auto ldsm_all = [&](const uint32_t st, int ks, uint32_t a[4][4], uint32_t b[4][4]) {
        #pragma unroll
        for (int mt = 0; mt < 4; mt++)
            asm volatile("ldmatrix.sync.aligned.m8n8.x4.shared.b16 {%0,%1,%2,%3}, [%4];"
                         : "=r"(a[mt][0]), "=r"(a[mt][1]), "=r"(a[mt][2]), "=r"(a[mt][3])
                         : "r"(st + aoff[mt] + ks * 32));
        #pragma unroll
        for (int np = 0; np < 4; np++)
            asm volatile("ldmatrix.sync.aligned.m8n8.x4.shared.b16 {%0,%1,%2,%3}, [%4];"
                         : "=r"(b[np][0]), "=r"(b[np][1]), "=r"(b[np][2]), "=r"(b[np][3])
                         : "r"(st + boff[np] + ks * 32));
    };

    auto mma_half = [&](uint32_t a[4][4], uint32_t b[4][4], int mt0, int mt1) {
        #pragma unroll
        for (int mt = mt0; mt < mt1; mt++)
            #pragma unroll
            for (int np = 0; np < 4; np++)
                #pragma unroll
                for (int h = 0; h < 2; h++) {
                    float* d = acc[mt][np * 2 + h];
                    asm volatile(
                        "mma.sync.aligned.m16n8k16.row.col.f32.f16.f16.f32 "
                        "{%0,%1,%2,%3}, {%4,%5,%6,%7}, {%8,%9}, {%0,%1,%2,%3};\n"
                        : "+f"(d[0]), "+f"(d[1]), "+f"(d[2]), "+f"(d[3])
                        : "r"(a[mt][0]), "r"(a[mt][1]), "r"(a[mt][2]), "r"(a[mt][3]),
                          "r"(b[np][2 * h]), "r"(b[np][2 * h + 1]));
                }
    };

    // prologue: stages 0,1,2 in flight
    issue(0, 0); issue(1, 1); issue(2, 2);

    // mainloop: one wait + one barrier per k-tile, 3-deep lookahead,
    // LDSM for ks1 pipelined UNDER the ks0 MMA chain (anti-convoy).
    #pragma unroll 1
    for (int kt = 0; kt < NKT; kt++) {
        if (kt + 2 < NKT) asm volatile("cp.async.wait_group 2;\n");
        else              asm volatile("cp.async.wait_group 0;\n");
        __syncthreads();

        const uint32_t st = sbase + (kt & 3) * STAGEB;
        uint32_t a0[4][4], b0[4][4], a1[4][4], b1[4][4];

        ldsm_all(st, 0, a0, b0);                 // ks0 fragments first (critical path)
        if (kt + 3 < NKT) issue(kt + 3, (kt + 3) & 3);  // LSU work under LDSM latency
        mma_half(a0, b0, 0, 2);                  // 16 MMAs: tensor pipe starts
        ldsm_all(st, 1, a1, b1);                 // ks1 loads under running MMA chain
        mma_half(a0, b0, 2, 4);                  // 16 MMAs covering ks1 LDSM latency
        mma_half(a1, b1, 0, 4);                  // 32 MMAs
    }

    // epilogue
    const int r = lane >> 2, cc = lane & 3;
    #pragma unroll
    for (int mt = 0; mt < 4; mt++) {
        #pragma unroll
        for (int n8 = 0; n8 < 8; n8++) {
            size_t row = (size_t)bm * BM + wm + mt * 16 + r;
            size_t col = (size_t)bn * BN + wn + n8 * 8 + cc * 2;
            float* d = acc[mt][n8];
            *(float2*)(out + row * DOUT + col)       = make_float2(d[0], d[1]);
            *(float2*)(out + (row + 8) * DOUT + col) = make_float2(d[2], d[3]);
        }
    }
}

extern "C" void kernel_launch(void* const* d_in, const int* in_sizes, int n_in,
                              void* d_out, int out_size) {
    const float* x     = (const float*)d_in[0];
    const float* base  = (const float*)d_in[1];
    const int*   mask  = (const int*)d_in[2];
    const float* coeff = (const float*)d_in[3];
    float* out = (float*)d_out;

    pack_x<<<dim3(MTOT / 128, NKT), 256>>>(x);
    pack_w<<<dim3(DOUT / 128, NKT), 256>>>(base, mask, coeff);

    const int smem = STAGES * STAGEB;   // 81920
    cudaFuncSetAttribute(gemm_fp16, cudaFuncAttributeMaxDynamicSharedMemorySize, smem);
    gemm_fp16<<<(MTOT / BM) * (DOUT / BN), 128, smem>>>(out);
}

// round 11
// speedup vs baseline: 1.3803x; 1.0028x over previous
#include <cuda_runtime.h>
#include <cuda_fp16.h>
#include <cstdint>

#define DIN   4096
#define DOUT  4096
#define MTOT  8192
#define BM    128
#define BN    128
#define BK    32
#define NKT   (DIN / BK)      // 128
#define STAGES 5
#define ASTAGE 10240          // 128 rows * 5 chunks * 16B (padded)
#define STAGEB 20480          // A + B per stage

// Packed fp16 operand tiles. Tile (mb,kt) / (nb,kt) = 4096 halves contiguous,
// chunk c (16B, 8 halves) = row (c>>2), kchunk (c&3). A: [M][K]; B: [N][K] (W transposed).
__device__ __half g_A[(size_t)MTOT * DIN];
__device__ __half g_B[(size_t)DOUT * DIN];

__device__ __forceinline__ uint32_t smem_u32(const void* p) {
    uint32_t a;
    asm("{ .reg .u64 t; cvta.to.shared.u64 t, %1; cvt.u32.u64 %0, t; }" : "=r"(a) : "l"(p));
    return a;
}
__device__ __forceinline__ void cp16(uint32_t dst, const void* src) {
    asm volatile("cp.async.cg.shared.global [%0], [%1], 16;\n" :: "r"(dst), "l"(src));
}

// ---------- fused prep: blocks [0,8192) pack x, [8192,12288) fuse+transpose W ----------
__global__ void __launch_bounds__(256) pack_all(const float* __restrict__ x,
                                                const float* __restrict__ base,
                                                const int* __restrict__ mask,
                                                const float* __restrict__ coeff) {
    __shared__ uint32_t sw32[128 * 17];              // used only by W blocks
    int bx = blockIdx.x;
    int t = threadIdx.x;

    if (bx < 8192) {
        // ---- pack x ----
        int mb = bx >> 7, kt = bx & 127;
        __half* tile = g_A + ((size_t)(mb * NKT + kt) << 12);
        #pragma unroll
        for (int it = 0; it < 2; it++) {
            int cid = it * 256 + t;                  // 512 chunks of 8 halves
            int row = cid >> 2, kc = cid & 3;
            const float4* src = (const float4*)(x + (size_t)(mb * 128 + row) * DIN + kt * BK + kc * 8);
            float4 f0 = src[0], f1 = src[1];
            __half2 h0 = __floats2half2_rn(f0.x, f0.y);
            __half2 h1 = __floats2half2_rn(f0.z, f0.w);
            __half2 h2 = __floats2half2_rn(f1.x, f1.y);
            __half2 h3 = __floats2half2_rn(f1.z, f1.w);
            uint4 v;
            v.x = *(uint32_t*)&h0; v.y = *(uint32_t*)&h1;
            v.z = *(uint32_t*)&h2; v.w = *(uint32_t*)&h3;
            *(uint4*)(tile + cid * 8) = v;
        }
    } else {
        // ---- fuse W = base + c*sign, transpose to [N][K] ----
        int wb = bx - 8192;
        int nb = wb >> 7, kt = wb & 127;
        float c = __ldg(coeff);
        int n = t & 127, hsel = t >> 7;
        #pragma unroll
        for (int i = 0; i < 8; i++) {
            int kp = hsel * 8 + i;
            size_t off0 = (size_t)(kt * BK + kp * 2) * DOUT + nb * 128 + n;
            size_t off1 = off0 + DOUT;
            float w0 = base[off0] + (mask[off0] ? c : -c);
            float w1 = base[off1] + (mask[off1] ? c : -c);
            __half2 h = __floats2half2_rn(w0, w1);
            sw32[n * 17 + kp] = *(uint32_t*)&h;
        }
        __syncthreads();
        __half* tile = g_B + ((size_t)(nb * NKT + kt) << 12);
        #pragma unroll
        for (int it = 0; it < 2; it++) {
            int cid = it * 256 + t;
            int nn = cid >> 2, kc = cid & 3;
            uint4 v;
            v.x = sw32[nn * 17 + kc * 4 + 0];
            v.y = sw32[nn * 17 + kc * 4 + 1];
            v.z = sw32[nn * 17 + kc * 4 + 2];
            v.w = sw32[nn * 17 + kc * 4 + 3];
            *(uint4*)(tile + cid * 8) = v;
        }
    }
}

// ---------- fp16 GEMM: 4 warps, 64x64 warp tiles, 5-stage pipelined ----------
__global__ void __launch_bounds__(128, 2) gemm_fp16(float* __restrict__ out) {
    extern __shared__ char smem[];
    const uint32_t sbase = smem_u32(smem);

    const int tid  = threadIdx.x;
    const int lane = tid & 31;
    const int warp = tid >> 5;                // 0..3
    const int wm = (warp & 1) * 64;           // warp tile 64(m) x 64(n)
    const int wn = (warp >> 1) * 64;

    // L2 block swizzle: 8 m-blocks share one n-block column
    int pid = blockIdx.x;
    int local = pid & 255, g = pid >> 8;
    int bm = (g << 3) + (local & 7);
    int bn = local >> 3;

    const __half* tA0 = g_A + ((size_t)bm * NKT << 12);
    const __half* tB0 = g_B + ((size_t)bn * NKT << 12);

    // ldmatrix per-lane base offsets (padded stride-5-chunk layout)
    const int j = lane >> 3, sub = lane & 7;
    uint32_t aoff[4], boff[4];
    #pragma unroll
    for (int mt = 0; mt < 4; mt++) {
        int m = wm + mt * 16 + (j & 1) * 8 + sub;
        aoff[mt] = (uint32_t)((m * 5 + (j >> 1)) << 4);
    }
    #pragma unroll
    for (int np = 0; np < 4; np++) {
        int n = wn + np * 16 + (j >> 1) * 8 + sub;
        boff[np] = (uint32_t)((n * 5 + (j & 1)) << 4) + ASTAGE;
    }

    float acc[4][8][4];
    #pragma unroll
    for (int a = 0; a < 4; a++)
        #pragma unroll
        for (int b = 0; b < 8; b++)
            #pragma unroll
            for (int d = 0; d < 4; d++) acc[a][b][d] = 0.f;

    auto issue = [&](int kt, int stage) {
        const __half* tA = tA0 + ((size_t)kt << 12);
        const __half* tB = tB0 + ((size_t)kt << 12);
        #pragma unroll
        for (int it = 0; it < 4; it++) {
            int cid = it * 128 + tid;             // 512 chunks each
            uint32_t d = sbase + stage * STAGEB + ((((cid >> 2) * 5) + (cid & 3)) << 4);
            cp16(d, tA + cid * 8);
            cp16(d + ASTAGE, tB + cid * 8);
        }
        asm volatile("cp.async.commit_group;\n");
    };

    auto ldsm_all = [&](const uint32_t st, int ks, uint32_t a[4][4], uint32_t b[4][4]) {
        #pragma unroll
        for (int mt = 0; mt < 4; mt++)
            asm volatile("ldmatrix.sync.aligned.m8n8.x4.shared.b16 {%0,%1,%2,%3}, [%4];"
                         : "=r"(a[mt][0]), "=r"(a[mt][1]), "=r"(a[mt][2]), "=r"(a[mt][3])
                         : "r"(st + aoff[mt] + ks * 32));
        #pragma unroll
        for (int np = 0; np < 4; np++)
            asm volatile("ldmatrix.sync.aligned.m8n8.x4.shared.b16 {%0,%1,%2,%3}, [%4];"
                         : "=r"(b[np][0]), "=r"(b[np][1]), "=r"(b[np][2]), "=r"(b[np][3])
                         : "r"(st + boff[np] + ks * 32));
    };

    auto mma_half = [&](uint32_t a[4][4], uint32_t b[4][4], int mt0, int mt1) {
        #pragma unroll
        for (int mt = mt0; mt < mt1; mt++)
            #pragma unroll
            for (int np = 0; np < 4; np++)
                #pragma unroll
                for (int h = 0; h < 2; h++) {
                    float* d = acc[mt][np * 2 + h];
                    asm volatile(
                        "mma.sync.aligned.m16n8k16.row.col.f32.f16.f16.f32 "
                        "{%0,%1,%2,%3}, {%4,%5,%6,%7}, {%8,%9}, {%0,%1,%2,%3};\n"
                        : "+f"(d[0]), "+f"(d[1]), "+f"(d[2]), "+f"(d[3])
                        : "r"(a[mt][0]), "r"(a[mt][1]), "r"(a[mt][2]), "r"(a[mt][3]),
                          "r"(b[np][2 * h]), "r"(b[np][2 * h + 1]));
                }
    };

    // prologue: stages 0..3 in flight (4-deep lookahead)
    issue(0, 0); issue(1, 1); issue(2, 2); issue(3, 3);

    // mainloop: one wait + one barrier per k-tile, 5 stages.
    // At top of iter kt: pending = {kt..kt+3} (while kt+3 < NKT) -> wait_group 3
    // completes group kt. issue targets stage (kt+4)%5 == (kt-1)%5, consumed by
    // all warps in iter kt-1, i.e. before this iteration's barrier.
    int s_cur = 0, s_nxt = 4;
    #pragma unroll 1
    for (int kt = 0; kt < NKT; kt++) {
        if (kt + 3 < NKT) asm volatile("cp.async.wait_group 3;\n");
        else              asm volatile("cp.async.wait_group 0;\n");
        __syncthreads();

        const uint32_t st = sbase + s_cur * STAGEB;
        uint32_t a0[4][4], b0[4][4], a1[4][4], b1[4][4];

        ldsm_all(st, 0, a0, b0);                 // ks0 fragments (critical path)
        if (kt + 4 < NKT) issue(kt + 4, s_nxt);  // LSU work under LDSM latency
        mma_half(a0, b0, 0, 2);                  // tensor pipe starts
        ldsm_all(st, 1, a1, b1);                 // ks1 loads under running MMAs
        mma_half(a0, b0, 2, 4);
        mma_half(a1, b1, 0, 4);

        if (++s_cur == STAGES) s_cur = 0;
        if (++s_nxt == STAGES) s_nxt = 0;
    }

    // epilogue
    const int r = lane >> 2, cc = lane & 3;
    #pragma unroll
    for (int mt = 0; mt < 4; mt++) {
        #pragma unroll
        for (int n8 = 0; n8 < 8; n8++) {
            size_t row = (size_t)bm * BM + wm + mt * 16 + r;
            size_t col = (size_t)bn * BN + wn + n8 * 8 + cc * 2;
            float* d = acc[mt][n8];
            *(float2*)(out + row * DOUT + col)       = make_float2(d[0], d[1]);
            *(float2*)(out + (row + 8) * DOUT + col) = make_float2(d[2], d[3]);
        }
    }
}

extern "C" void kernel_launch(void* const* d_in, const int* in_sizes, int n_in,
                              void* d_out, int out_size) {
    const float* x     = (const float*)d_in[0];
    const float* base  = (const float*)d_in[1];
    const int*   mask  = (const int*)d_in[2];
    const float* coeff = (const float*)d_in[3];
    float* out = (float*)d_out;

    pack_all<<<12288, 256>>>(x, base, mask, coeff);

    const int smem = STAGES * STAGEB;   // 102400
    cudaFuncSetAttribute(gemm_fp16, cudaFuncAttributeMaxDynamicSharedMemorySize, smem);
    gemm_fp16<<<(MTOT / BM) * (DOUT / BN), 128, smem>>>(out);
}